// round 9
// baseline (speedup 1.0000x reference)
#include <cuda_runtime.h>
#include <cstdint>
#include <cmath>

#define GH 512
#define GK 50
#define GT 1024
#define GB 128
#define BPP 52

// Packed fp32x2 FMA (sm_103a): acc = x * w + acc
#define FFMA2(acc, x, w) \
    asm("fma.rn.f32x2 %0, %1, %2, %0;" : "+l"(acc) : "l"(x), "l"(w))

// ---------------------------------------------------------------------------
// Thread-fused persistent kernel: ONE group of 224 threads per batch does
// BOTH the Viterbi DP (round-3 proven structure) and the feats GEMM.
// Threads 0-127 each own one feats row per 128-step block; each DP step they
// also execute a 4-k GEMM micro-step (100 FFMA2 + broadcast LDS) that the
// warp scheduler issues inside the DP chain's latency shadows. Block m+1 is
// produced during block m's DP steps into the other ring half; the per-step
// __syncthreads is the only synchronization (no flags, no named barriers).
// ---------------------------------------------------------------------------
// smem byte offsets
#define SM_WT    0                       // Wt[512][52] floats = 106496
#define SM_RING  106496                  // ring[2][128][52] floats = 53248
#define SM_BP    159744                  // bp 1023*52 = 53196 (pad 53248)
#define SM_VBUF  212992                  // 2*64 floats = 512
#define SM_RED   213504                  // 64 floats = 256
#define SM_TAGS  213760                  // 1024 bytes
#define SM_BIAS  214784                  // 64 floats = 256
#define SM_TOTAL 215040

// Pairwise argmax tree (select-form). Adjacent pairs keep index-ordered
// subranges; strict '>' == jnp.argmax first-max tie-breaking.
template <int Wd>
__device__ __forceinline__ void argmax_tree(float* val, int* id) {
    if constexpr (Wd > 1) {
        constexpr int P = Wd >> 1;
#pragma unroll
        for (int m = 0; m < P; m++) {
            bool g = val[2 * m + 1] > val[2 * m];
            val[m] = g ? val[2 * m + 1] : val[2 * m];
            id[m]  = g ? id[2 * m + 1]  : id[2 * m];
        }
        if constexpr (Wd & 1) { val[P] = val[Wd - 1]; id[P] = id[Wd - 1]; }
        argmax_tree<((Wd + 1) >> 1)>(val, id);
    }
}

// One 4-k GEMM micro-step: acc[0..24] (f32x2 pairs of 50 outputs) += cur * Wt
__device__ __forceinline__ void gemm4(unsigned long long* acc, float4 cur,
                                      const float* Wt, int kk) {
#pragma unroll
    for (int u = 0; u < 4; u++) {
        const float xv = (&cur.x)[u];
        unsigned long long X;
        asm("mov.b64 %0, {%1, %1};" : "=l"(X) : "r"(__float_as_uint(xv)));
        const float* wr = Wt + (kk + u) * 52;
#pragma unroll
        for (int q = 0; q < 12; q++) {
            ulonglong2 w = *reinterpret_cast<const ulonglong2*>(wr + q * 4);
            FFMA2(acc[2 * q],     X, w.x);
            FFMA2(acc[2 * q + 1], X, w.y);
        }
        unsigned long long wl = *reinterpret_cast<const unsigned long long*>(wr + 48);
        FFMA2(acc[24], X, wl);
    }
}

// Store a finished row: bias + 25 float2 to ring; reset accumulators.
__device__ __forceinline__ void row_store(unsigned long long* acc, float* dst,
                                          const float* sbias) {
#pragma unroll
    for (int p = 0; p < 25; p++) {
        float2 a = *reinterpret_cast<float2*>(&acc[p]);
        a.x += sbias[2 * p];
        a.y += sbias[2 * p + 1];
        reinterpret_cast<float2*>(dst)[p] = a;
        acc[p] = 0ull;
    }
}

__global__ __launch_bounds__(224, 1) void crf_fused_kernel(
    const float* __restrict__ hidden, const float* __restrict__ W,
    const float* __restrict__ bias, const float* __restrict__ trans,
    const float* __restrict__ startt, const float* __restrict__ stopt,
    float* __restrict__ out) {
    extern __shared__ char smem[];
    float* Wt   = reinterpret_cast<float*>(smem + SM_WT);
    float* ring = reinterpret_cast<float*>(smem + SM_RING);   // [2][128][52]
    unsigned char* bp = reinterpret_cast<unsigned char*>(smem + SM_BP);
    float* vbuf = reinterpret_cast<float*>(smem + SM_VBUF);
    float* red  = reinterpret_cast<float*>(smem + SM_RED);
    unsigned char* tags = reinterpret_cast<unsigned char*>(smem + SM_TAGS);
    float* sbias = reinterpret_cast<float*>(smem + SM_BIAS);

    const int b = blockIdx.x;
    const int tid = threadIdx.x;

    // ---- setup ----
    // W transpose: W[k*512+h] -> Wt[h*52+k]
    for (int idx = tid; idx < GK * GH; idx += 224) {
        int k = idx >> 9;
        int h = idx & 511;
        Wt[h * 52 + k] = W[idx];
    }
    if (tid < GK) sbias[tid] = bias[tid];

    // DP thread mapping (round-3 proven): j = tid>>2, r = tid&3
    const int j = tid >> 2;
    const int r = tid & 3;
    const int i0 = r * 13;
    float tr[13];
#pragma unroll
    for (int ii = 0; ii < 13; ii++) {
        int i = i0 + ii;
        tr[ii] = (j < GK && i < GK) ? trans[i * GK + j] : -INFINITY;
    }
    if (tid >= GK && tid < 64) { vbuf[tid] = -INFINITY; vbuf[64 + tid] = -INFINITY; }

    __syncthreads();   // Wt + sbias ready

    // ---- GEMM state (threads 0-127 own one row per block) ----
    unsigned long long acc[25];
#pragma unroll
    for (int p = 0; p < 25; p++) acc[p] = 0ull;
    const float* hrow = nullptr;   // current block row base (float)
    float4 hpf = make_float4(0.f, 0.f, 0.f, 0.f);

    if (tid < 128) {
        // Prologue: compute block 0 (rows 0..127) fully
        const float* h0 = hidden + ((size_t)b * GT + tid) * GH;
        const float4* h4 = reinterpret_cast<const float4*>(h0);
        float4 p0 = h4[0], p1 = h4[1], p2 = h4[2], p3 = h4[3];
        for (int kc = 0; kc < 128; kc += 4) {
            float4 c0 = p0, c1 = p1, c2 = p2, c3 = p3;
            if (kc < 124) { p0 = h4[kc + 4]; p1 = h4[kc + 5]; p2 = h4[kc + 6]; p3 = h4[kc + 7]; }
            gemm4(acc, c0, Wt, 4 * kc);
            gemm4(acc, c1, Wt, 4 * kc + 4);
            gemm4(acc, c2, Wt, 4 * kc + 8);
            gemm4(acc, c3, Wt, 4 * kc + 12);
        }
        row_store(acc, ring + tid * 52, sbias);   // half 0

        // Begin block 1: micro-step 0 (k 0..3) + prefetch for micro-step 1
        hrow = h0 + 128 * GH;
        const float4* hn = reinterpret_cast<const float4*>(hrow);
        gemm4(acc, hn[0], Wt, 0);
        hpf = hn[1];
    }
    __syncthreads();   // block 0 feats visible

    // DP init: v(t=0)
    if (r == 0 && j < GK) vbuf[j] = ring[j] + startt[j];
    __syncthreads();

    // ---- main loop: DP step + GEMM micro-step, one barrier per step ----
    for (int tt = 1; tt < GT; tt++) {
        // DP compute
        const float* vr = vbuf + (((tt - 1) & 1) << 6);
        float cand[13];
        int id[13];
#pragma unroll
        for (int ii = 0; ii < 13; ii++) {
            cand[ii] = vr[i0 + ii] + tr[ii];
            id[ii] = i0 + ii;
        }
        argmax_tree<13>(cand, id);
        float best = cand[0];
        int bi = id[0];

        float ov = __shfl_xor_sync(0xffffffffu, best, 1);
        int   oi = __shfl_xor_sync(0xffffffffu, bi, 1);
        bool g1 = (ov > best) || (ov == best && oi < bi);
        best = g1 ? ov : best;
        bi   = g1 ? oi : bi;
        ov = __shfl_xor_sync(0xffffffffu, best, 2);
        oi = __shfl_xor_sync(0xffffffffu, bi, 2);
        bool g2 = (ov > best) || (ov == best && oi < bi);
        best = g2 ? ov : best;
        bi   = g2 ? oi : bi;

        if (r == 1 && j < GK) {
            float feat = ring[((tt >> 7) & 1) * 6656 + (tt & 127) * 52 + j];
            vbuf[((tt & 1) << 6) + j] = feat + best;
        } else if (r == 0 && j < GK) {
            bp[(tt - 1) * BPP + j] = (unsigned char)bi;
        }

        // GEMM micro-step tt: k = 4*(tt&127) of block (tt>>7)+1
        if (tid < 128 && tt < 896) {
            const int ks = tt & 127;
            float4 cur = hpf;
            if (ks < 127) {
                hpf = reinterpret_cast<const float4*>(hrow)[ks + 1];
            } else if (tt < 895 + 1 && tt != 895) {
                // unreachable placeholder (ks==127 handled below)
            }
            gemm4(acc, cur, Wt, 4 * ks);
            if (ks == 127) {
                // finish row of block bm = (tt>>7)+1 -> ring half bm&1
                const int bm = (tt >> 7) + 1;
                row_store(acc, ring + (bm & 1) * 6656 + tid * 52, sbias);
                if (tt < 895) {            // start next block's row
                    hrow += 128 * GH;
                    const float4* hn = reinterpret_cast<const float4*>(hrow);
                    hpf = hn[0];
                }
            }
        }
        __syncthreads();
    }

    // ---- final reduction + backtrace (round-3 proven) ----
    if (r == 0 && j < GK) red[j] = vbuf[64 + j] + stopt[j];
    __syncthreads();

    if (tid == 0) {
        float best = -INFINITY;
        int bj = 0;
        for (int k = 0; k < GK; k++) {
            float s = red[k];
            if (s > best) { best = s; bj = k; }
        }
        out[b] = best;
        int tag = bj;
        tags[GT - 1] = (unsigned char)tag;
        for (int k = GT - 2; k >= 0; k--) {
            tag = bp[k * BPP + tag];
            tags[k] = (unsigned char)tag;
        }
    }
    __syncthreads();

    float* tout = out + GB + (size_t)b * GT;
    for (int k = tid; k < GT; k += 224) tout[k] = (float)tags[k];
}

extern "C" void kernel_launch(void* const* d_in, const int* in_sizes, int n_in,
                              void* d_out, int out_size) {
    const float* hidden = (const float*)d_in[0];
    const float* W      = (const float*)d_in[1];
    const float* bias   = (const float*)d_in[2];
    const float* trans  = (const float*)d_in[3];
    const float* startt = (const float*)d_in[4];
    const float* stopt  = (const float*)d_in[5];
    float* out = (float*)d_out;

    cudaFuncSetAttribute(crf_fused_kernel,
                         cudaFuncAttributeMaxDynamicSharedMemorySize, SM_TOTAL);
    crf_fused_kernel<<<GB, 224, SM_TOTAL>>>(hidden, W, bias, trans,
                                            startt, stopt, out);
}